// round 3
// baseline (speedup 1.0000x reference)
#include <cuda_runtime.h>
#include <cstdint>

#define N_ENTITIES 100000
#define N_USERS    50000
#define N_FACTORS  4
#define N_RELATIONS 32
#define N_META     8
#define CHANNEL    64
#define N_EDGES    1600000
#define NNZ_CNT    1000000

// ------------------------- device-global scratch ---------------------------
__device__ int  g_ecnt[N_ENTITIES];          // histogram, then scatter cursor
__device__ int  g_eoff[N_ENTITIES + 1];      // CSR offsets for edges by head
__device__ int  g_ucnt[N_USERS];
__device__ int  g_uoff[N_USERS + 1];
__device__ int2 g_sorted_e[N_EDGES];         // {tail, rel_idx} binned by head
__device__ int2 g_sorted_m[NNZ_CNT];         // {col, bits(val)} binned by row
__device__ float g_disen[N_FACTORS * CHANNEL];

// ---------------------------------------------------------------------------
// 0) zero histograms
// ---------------------------------------------------------------------------
__global__ void zero_kernel() {
    int i = blockIdx.x * blockDim.x + threadIdx.x;
    if (i < N_ENTITIES) g_ecnt[i] = 0;
    if (i < N_USERS)    g_ucnt[i] = 0;
}

// ---------------------------------------------------------------------------
// 1) histogram: edge heads + nnz rows in one launch
// ---------------------------------------------------------------------------
__global__ void hist_kernel(const int* __restrict__ head,
                            const int* __restrict__ mrow) {
    int i = blockIdx.x * blockDim.x + threadIdx.x;
    if (i < N_EDGES) {
        atomicAdd(&g_ecnt[head[i]], 1);
    } else if (i < N_EDGES + NNZ_CNT) {
        atomicAdd(&g_ucnt[mrow[i - N_EDGES]], 1);
    }
}

// ---------------------------------------------------------------------------
// 2) exclusive scan (single block per array; block 0 = entities, 1 = users)
//    also re-zeroes the count array so it can serve as the scatter cursor
// ---------------------------------------------------------------------------
__global__ void scan_kernel() {
    int* cnt;  int* off;  int n;
    if (blockIdx.x == 0) { cnt = g_ecnt; off = g_eoff; n = N_ENTITIES; }
    else                 { cnt = g_ucnt; off = g_uoff; n = N_USERS;    }

    const int T = 1024;
    int tid = threadIdx.x;
    int chunk = (n + T - 1) / T;
    int start = tid * chunk;
    int stop  = min(start + chunk, n);

    int s = 0;
    for (int i = start; i < stop; i++) s += cnt[i];

    __shared__ int sh[T];
    sh[tid] = s;
    __syncthreads();
    // Hillis-Steele inclusive scan
    #pragma unroll
    for (int d = 1; d < T; d <<= 1) {
        int t = (tid >= d) ? sh[tid - d] : 0;
        __syncthreads();
        sh[tid] += t;
        __syncthreads();
    }
    int run = sh[tid] - s;   // exclusive prefix of this thread's chunk

    for (int i = start; i < stop; i++) {
        int c = cnt[i];
        off[i] = run;
        run += c;
        cnt[i] = 0;          // cursor for the scatter pass
    }
    if (tid == T - 1) off[n] = run;
}

// ---------------------------------------------------------------------------
// 3) scatter payloads into bins
// ---------------------------------------------------------------------------
__global__ void scatter_kernel(const int* __restrict__ head,
                               const int* __restrict__ tail,
                               const int* __restrict__ etype,
                               const int* __restrict__ mrow,
                               const int* __restrict__ mcol,
                               const float* __restrict__ mval) {
    int i = blockIdx.x * blockDim.x + threadIdx.x;
    if (i < N_EDGES) {
        int h = head[i];
        int pos = g_eoff[h] + atomicAdd(&g_ecnt[h], 1);
        g_sorted_e[pos] = make_int2(tail[i], etype[i] - 1);
    } else if (i < N_EDGES + NNZ_CNT) {
        int j = i - N_EDGES;
        int r = mrow[j];
        int pos = g_uoff[r] + atomicAdd(&g_ucnt[r], 1);
        g_sorted_m[pos] = make_int2(mcol[j], __float_as_int(mval[j]));
    }
}

// ---------------------------------------------------------------------------
// 4) disen_weight = softmax(disen_weight_att, -1) @ weight   (4 x 64)
// ---------------------------------------------------------------------------
__global__ void disen_kernel(const float* __restrict__ att,
                             const float* __restrict__ weight) {
    int c = threadIdx.x;
    if (c >= CHANNEL) return;
    #pragma unroll
    for (int f = 0; f < N_FACTORS; f++) {
        float a[N_META];
        float m = -1e30f;
        #pragma unroll
        for (int j = 0; j < N_META; j++) { a[j] = att[f * N_META + j]; m = fmaxf(m, a[j]); }
        float s = 0.0f;
        #pragma unroll
        for (int j = 0; j < N_META; j++) { a[j] = __expf(a[j] - m); s += a[j]; }
        float inv = 1.0f / s;
        float acc = 0.0f;
        #pragma unroll
        for (int j = 0; j < N_META; j++) acc += a[j] * inv * weight[j * CHANNEL + c];
        g_disen[f * CHANNEL + c] = acc;
    }
}

// ---------------------------------------------------------------------------
// 5) edge gather: one warp per entity; register accumulation; fused mean
// ---------------------------------------------------------------------------
__global__ void edge_gather_kernel(const float* __restrict__ ent,
                                   const float* __restrict__ relw,   // (31,64)
                                   float* __restrict__ out_ent) {
    __shared__ float s_rel[(N_RELATIONS - 1) * CHANNEL];
    for (int i = threadIdx.x; i < (N_RELATIONS - 1) * CHANNEL; i += blockDim.x)
        s_rel[i] = relw[i];
    __syncthreads();

    int h    = blockIdx.x * (blockDim.x >> 5) + (threadIdx.x >> 5);
    int lane = threadIdx.x & 31;
    if (h >= N_ENTITIES) return;

    int beg = g_eoff[h];
    int end = g_eoff[h + 1];
    int deg = end - beg;

    float2 eh  = *(const float2*)&ent[(size_t)h * CHANNEL + lane * 2];
    float2 acc = make_float2(0.f, 0.f);

    #pragma unroll 2
    for (int j = beg; j < end; j++) {
        int2 p = g_sorted_e[j];                 // uniform load, broadcast
        int  t = p.x, r = p.y;
        float2 rel = *(const float2*)&s_rel[r * CHANNEL + lane * 2];
        float d = eh.x * rel.x + eh.y * rel.y;
        #pragma unroll
        for (int o = 16; o > 0; o >>= 1) d += __shfl_xor_sync(0xFFFFFFFFu, d, o);
        float att = 1.0f / (1.0f + __expf(-d));
        float2 et = *(const float2*)&ent[(size_t)t * CHANNEL + lane * 2];
        acc.x += att * et.x * rel.x;
        acc.y += att * et.y * rel.y;
    }

    float inv = 1.0f / (float)max(deg, 1);
    float2* o = (float2*)&out_ent[(size_t)h * CHANNEL + lane * 2];
    *o = make_float2(acc.x * inv, acc.y * inv);
}

// ---------------------------------------------------------------------------
// 6) user gather: one warp per user; fused softmax score + disen blend
// ---------------------------------------------------------------------------
__global__ void user_gather_kernel(const float* __restrict__ ent,
                                   const float* __restrict__ user_emb,
                                   const float* __restrict__ latent,
                                   float* __restrict__ out_user) {
    __shared__ float s_lat[N_FACTORS * CHANNEL];
    __shared__ float s_dis[N_FACTORS * CHANNEL];
    for (int i = threadIdx.x; i < N_FACTORS * CHANNEL; i += blockDim.x) {
        s_lat[i] = latent[i];
        s_dis[i] = g_disen[i];
    }
    __syncthreads();

    int u    = blockIdx.x * (blockDim.x >> 5) + (threadIdx.x >> 5);
    int lane = threadIdx.x & 31;
    if (u >= N_USERS) return;

    // --- sparse-mm gather ---
    int beg = g_uoff[u];
    int end = g_uoff[u + 1];
    float2 acc = make_float2(0.f, 0.f);
    #pragma unroll 2
    for (int j = beg; j < end; j++) {
        int2 p = g_sorted_m[j];
        int   c = p.x;
        float v = __int_as_float(p.y);
        float2 e = *(const float2*)&ent[(size_t)c * CHANNEL + lane * 2];
        acc.x += v * e.x;
        acc.y += v * e.y;
    }

    // --- score softmax + disen blend ---
    float2 ue = *(const float2*)&user_emb[(size_t)u * CHANNEL + lane * 2];
    float s[N_FACTORS];
    #pragma unroll
    for (int f = 0; f < N_FACTORS; f++) {
        float d = ue.x * s_lat[f * CHANNEL + lane * 2]
                + ue.y * s_lat[f * CHANNEL + lane * 2 + 1];
        #pragma unroll
        for (int o = 16; o > 0; o >>= 1) d += __shfl_xor_sync(0xFFFFFFFFu, d, o);
        s[f] = d;
    }
    float m = fmaxf(fmaxf(s[0], s[1]), fmaxf(s[2], s[3]));
    float sum = 0.0f;
    #pragma unroll
    for (int f = 0; f < N_FACTORS; f++) { s[f] = __expf(s[f] - m); sum += s[f]; }
    float inv = 1.0f / sum;

    float cx = 0.0f, cy = 0.0f;
    #pragma unroll
    for (int f = 0; f < N_FACTORS; f++) {
        float sc = s[f] * inv;
        cx += sc * s_dis[f * CHANNEL + lane * 2];
        cy += sc * s_dis[f * CHANNEL + lane * 2 + 1];
    }

    float2* o = (float2*)&out_user[(size_t)u * CHANNEL + lane * 2];
    *o = make_float2(acc.x * (1.0f + cx), acc.y * (1.0f + cy));
}

// ---------------------------------------------------------------------------
extern "C" void kernel_launch(void* const* d_in, const int* in_sizes, int n_in,
                              void* d_out, int out_size)
{
    const float* entity_emb = (const float*)d_in[0];
    const float* user_emb   = (const float*)d_in[1];
    const float* latent_emb = (const float*)d_in[2];
    const int*   head       = (const int*)d_in[3];
    const int*   tail       = (const int*)d_in[4];
    const int*   edge_type  = (const int*)d_in[5];
    const int*   mat_row    = (const int*)d_in[6];
    const int*   mat_col    = (const int*)d_in[7];
    const float* mat_val    = (const float*)d_in[8];
    const float* rel_w      = (const float*)d_in[9];
    const float* weight     = (const float*)d_in[10];
    const float* disen_att  = (const float*)d_in[11];

    float* out      = (float*)d_out;
    float* out_ent  = out;                                 // (N_ENTITIES, 64)
    float* out_user = out + (size_t)N_ENTITIES * CHANNEL;  // (N_USERS, 64)

    zero_kernel<<<(N_ENTITIES + 255) / 256, 256>>>();
    hist_kernel<<<(N_EDGES + NNZ_CNT + 255) / 256, 256>>>(head, mat_row);
    scan_kernel<<<2, 1024>>>();
    scatter_kernel<<<(N_EDGES + NNZ_CNT + 255) / 256, 256>>>(
        head, tail, edge_type, mat_row, mat_col, mat_val);
    disen_kernel<<<1, 64>>>(disen_att, weight);

    edge_gather_kernel<<<(N_ENTITIES + 7) / 8, 256>>>(entity_emb, rel_w, out_ent);
    user_gather_kernel<<<(N_USERS + 7) / 8, 256>>>(entity_emb, user_emb,
                                                   latent_emb, out_user);
}